// round 4
// baseline (speedup 1.0000x reference)
#include <cuda_runtime.h>
#include <cuda_fp16.h>

#define W0 512
#define H0 512
#define BATCH 32
#define TH 16   // pixel rows per thread column

// Fused pair tables: entry e = p*256+q holds 8 halves:
//   [0..3] = 0.5 * T[p*256+q]  ("self")
//   [4..7] = 0.5 * T[q*256+p]  ("other")
__device__ uint4 g_H2[65536];
__device__ uint4 g_V2[65536];
__device__ uint4 g_D2[65536];

static __device__ __forceinline__ unsigned pack_h2(float a, float b) {
    __half2 h = __floats2half2_rn(a, b);
    return *reinterpret_cast<unsigned*>(&h);
}

__global__ void prep_kernel(const float4* __restrict__ hw,
                            const float4* __restrict__ dw,
                            const float4* __restrict__ vw)
{
    int e = blockIdx.x * blockDim.x + threadIdx.x;   // p*256 + q
    int p = e >> 8, q = e & 255;
    int et = (q << 8) | p;
    {
        float4 s = hw[e], o = hw[et];
        uint4 u;
        u.x = pack_h2(0.5f * s.x, 0.5f * s.y);
        u.y = pack_h2(0.5f * s.z, 0.5f * s.w);
        u.z = pack_h2(0.5f * o.x, 0.5f * o.y);
        u.w = pack_h2(0.5f * o.z, 0.5f * o.w);
        g_H2[e] = u;
    }
    {
        float4 s = vw[e], o = vw[et];
        uint4 u;
        u.x = pack_h2(0.5f * s.x, 0.5f * s.y);
        u.y = pack_h2(0.5f * s.z, 0.5f * s.w);
        u.z = pack_h2(0.5f * o.x, 0.5f * o.y);
        u.w = pack_h2(0.5f * o.z, 0.5f * o.w);
        g_V2[e] = u;
    }
    {
        float4 s = dw[e], o = dw[et];
        uint4 u;
        u.x = pack_h2(0.5f * s.x, 0.5f * s.y);
        u.y = pack_h2(0.5f * s.z, 0.5f * s.w);
        u.z = pack_h2(0.5f * o.x, 0.5f * o.y);
        u.w = pack_h2(0.5f * o.z, 0.5f * o.w);
        g_D2[e] = u;
    }
}

// ---- accumulation helpers (x,y are packed half2 pairs = 4 weights w=0..3) ----
static __device__ __forceinline__ void acc_fwd(float* a, unsigned x, unsigned y) {
    float2 p = __half22float2(*reinterpret_cast<__half2*>(&x));
    float2 q = __half22float2(*reinterpret_cast<__half2*>(&y));
    a[0] += p.x; a[1] += p.y; a[2] += q.x; a[3] += q.y;
}
static __device__ __forceinline__ void acc_rev(float* a, unsigned x, unsigned y) {
    float2 p = __half22float2(*reinterpret_cast<__half2*>(&x));
    float2 q = __half22float2(*reinterpret_cast<__half2*>(&y));
    a[3] += p.x; a[2] += p.y; a[1] += q.x; a[0] += q.y;
}
static __device__ __forceinline__ void acc_dl(float* a, unsigned x, unsigned y) {
    float2 p = __half22float2(*reinterpret_cast<__half2*>(&x));
    float2 q = __half22float2(*reinterpret_cast<__half2*>(&y));
    a[1] += p.x; a[3] += p.y; a[0] += q.x; a[2] += q.y;
}
static __device__ __forceinline__ void acc_ur(float* a, unsigned x, unsigned y) {
    float2 p = __half22float2(*reinterpret_cast<__half2*>(&x));
    float2 q = __half22float2(*reinterpret_cast<__half2*>(&y));
    a[2] += p.x; a[0] += p.y; a[3] += q.x; a[1] += q.y;
}

// Pair-index selectors for __byte_perm (result then masked to 16 bits):
//  H  (wa_j<<8 | wa_{j+1}): j=1:0x4412  j=2:0x4423  lane0 j=0:0x4401   (b=0)
//  V  (wa_j<<8 | wb_j    ): j=1:0x4415  j=2:0x4426
//  Dm (wa_j<<8 | wb_{j+1}): j=1:0x4416  j=2:0x4427  lane0 j=0:0x4405
//  Da (wa_j<<8 | wb_{j-1}): j=2:0x4425  j=3:0x4436  lane0 j=1:0x4414

__global__ __launch_bounds__(128) void hdvlut_kernel(
    const int* __restrict__ img,
    float* __restrict__ out)
{
    const unsigned FULL = 0xFFFFFFFFu;
    int lane = threadIdx.x & 31;
    int x0 = (blockIdx.x * blockDim.x + threadIdx.x) * 2;
    int y0 = blockIdx.y * TH;
    int b  = blockIdx.z;

    const int* im = img + (size_t)b * (H0 * W0);

    int xs0 = max(x0 - 1, 0);
    int xs3 = min(x0 + 2, W0 - 1);

#define LOADROW(yy, dst) do {                                            \
        int _y = min(max((yy), 0), H0 - 1);                              \
        const int* _rp = im + _y * W0;                                   \
        unsigned _a0 = (unsigned)__ldg(_rp + xs0);                       \
        unsigned _a1 = (unsigned)__ldg(_rp + x0);                        \
        unsigned _a2 = (unsigned)__ldg(_rp + x0 + 1);                    \
        unsigned _a3 = (unsigned)__ldg(_rp + xs3);                       \
        dst = _a0 | (_a1 << 8) | (_a2 << 16) | (_a3 << 24);              \
    } while (0)

    unsigned wa, wb;
    LOADROW(y0 - 1, wa);
    LOADROW(y0,     wb);

    float accP[2][4], accC[2][4];
#pragma unroll
    for (int c = 0; c < 2; c++)
#pragma unroll
        for (int w = 0; w < 4; w++) { accP[c][w] = 0.0f; accC[c][w] = 0.0f; }

    float* outp = out + (size_t)b * (2 * H0) * (2 * W0) + 2 * x0;

    // ---------- prologue: site row iy = 0 (others only -> accC) ----------
    {
        uint4 v1 = __ldg(&g_V2[__byte_perm(wa, wb, 0x4415) & 0xFFFF]);
        uint4 v2 = __ldg(&g_V2[__byte_perm(wa, wb, 0x4426) & 0xFFFF]);
        uint4 m1 = __ldg(&g_D2[__byte_perm(wa, wb, 0x4416) & 0xFFFF]);
        uint4 m2 = __ldg(&g_D2[__byte_perm(wa, wb, 0x4427) & 0xFFFF]);
        uint4 a2 = __ldg(&g_D2[__byte_perm(wa, wb, 0x4425) & 0xFFFF]);
        uint4 a3 = __ldg(&g_D2[__byte_perm(wa, wb, 0x4436) & 0xFFFF]);

        unsigned m2z = __shfl_up_sync(FULL, m2.z, 1);
        unsigned m2w = __shfl_up_sync(FULL, m2.w, 1);
        if (lane == 0) {
            uint4 m0 = __ldg(&g_D2[__byte_perm(wa, wb, 0x4405) & 0xFFFF]);
            m2z = m0.z; m2w = m0.w;
        }
        acc_rev(accC[0], v1.z, v1.w);
        acc_rev(accC[1], v2.z, v2.w);
        acc_rev(accC[1], m1.z, m1.w);
        acc_rev(accC[0], m2z, m2w);
        acc_ur (accC[0], a2.z, a2.w);
        acc_ur (accC[1], a3.z, a3.w);
    }
    // rotate
#pragma unroll
    for (int c = 0; c < 2; c++)
#pragma unroll
        for (int w = 0; w < 4; w++) { accP[c][w] = accC[c][w]; accC[c][w] = 0.0f; }
    wa = wb;
    LOADROW(y0 + 1, wb);

    // ---------- main loop: site rows iy = 1 .. TH-1 ----------
#pragma unroll 4
    for (int iy = 1; iy <= TH - 1; iy++) {
        uint4 v1 = __ldg(&g_V2[__byte_perm(wa, wb, 0x4415) & 0xFFFF]);
        uint4 v2 = __ldg(&g_V2[__byte_perm(wa, wb, 0x4426) & 0xFFFF]);
        uint4 m1 = __ldg(&g_D2[__byte_perm(wa, wb, 0x4416) & 0xFFFF]);
        uint4 m2 = __ldg(&g_D2[__byte_perm(wa, wb, 0x4427) & 0xFFFF]);
        uint4 a2 = __ldg(&g_D2[__byte_perm(wa, wb, 0x4425) & 0xFFFF]);
        uint4 a3 = __ldg(&g_D2[__byte_perm(wa, wb, 0x4436) & 0xFFFF]);
        uint4 h1 = __ldg(&g_H2[__byte_perm(wa, 0,  0x4412)]);
        uint4 h2 = __ldg(&g_H2[__byte_perm(wa, 0,  0x4423)]);

        unsigned m2z = __shfl_up_sync(FULL, m2.z, 1);
        unsigned m2w = __shfl_up_sync(FULL, m2.w, 1);
        unsigned a3x = __shfl_up_sync(FULL, a3.x, 1);
        unsigned a3y = __shfl_up_sync(FULL, a3.y, 1);
        unsigned h2z = __shfl_up_sync(FULL, h2.z, 1);
        unsigned h2w = __shfl_up_sync(FULL, h2.w, 1);
        if (lane == 0) {
            uint4 m0 = __ldg(&g_D2[__byte_perm(wa, wb, 0x4405) & 0xFFFF]);
            uint4 a1 = __ldg(&g_D2[__byte_perm(wa, wb, 0x4414) & 0xFFFF]);
            uint4 h0 = __ldg(&g_H2[__byte_perm(wa, 0,  0x4401)]);
            m2z = m0.z; m2w = m0.w;
            a3x = a1.x; a3y = a1.y;
            h2z = h0.z; h2w = h0.w;
        }

        // self contributions -> accP (pixel row iy-1)
        acc_fwd(accP[0], v1.x, v1.y);
        acc_fwd(accP[1], v2.x, v2.y);
        acc_fwd(accP[0], m1.x, m1.y);
        acc_fwd(accP[1], m2.x, m2.y);
        acc_dl (accP[1], a2.x, a2.y);
        acc_dl (accP[0], a3x,  a3y);
        // H row iy -> accP
        acc_fwd(accP[0], h1.x, h1.y);
        acc_rev(accP[1], h1.z, h1.w);
        acc_fwd(accP[1], h2.x, h2.y);
        acc_rev(accP[0], h2z,  h2w);
        // other contributions -> accC (pixel row iy)
        acc_rev(accC[0], v1.z, v1.w);
        acc_rev(accC[1], v2.z, v2.w);
        acc_rev(accC[1], m1.z, m1.w);
        acc_rev(accC[0], m2z,  m2w);
        acc_ur (accC[0], a2.z, a2.w);
        acc_ur (accC[1], a3.z, a3.w);

        // store finished pixel row (y0+iy-1)
        {
            size_t r0 = (size_t)(2 * (y0 + iy - 1)) * (2 * W0);
            float4 o0 = make_float4(accP[0][0], accP[0][1], accP[1][0], accP[1][1]);
            float4 o1 = make_float4(accP[0][2], accP[0][3], accP[1][2], accP[1][3]);
            *reinterpret_cast<float4*>(outp + r0)            = o0;
            *reinterpret_cast<float4*>(outp + r0 + 2 * W0)   = o1;
        }
        // rotate
#pragma unroll
        for (int c = 0; c < 2; c++)
#pragma unroll
            for (int w = 0; w < 4; w++) { accP[c][w] = accC[c][w]; accC[c][w] = 0.0f; }
        wa = wb;
        LOADROW(y0 + iy + 1, wb);
    }

    // ---------- epilogue: site row iy = TH (self + H only -> accP) ----------
    {
        uint4 v1 = __ldg(&g_V2[__byte_perm(wa, wb, 0x4415) & 0xFFFF]);
        uint4 v2 = __ldg(&g_V2[__byte_perm(wa, wb, 0x4426) & 0xFFFF]);
        uint4 m1 = __ldg(&g_D2[__byte_perm(wa, wb, 0x4416) & 0xFFFF]);
        uint4 m2 = __ldg(&g_D2[__byte_perm(wa, wb, 0x4427) & 0xFFFF]);
        uint4 a2 = __ldg(&g_D2[__byte_perm(wa, wb, 0x4425) & 0xFFFF]);
        uint4 a3 = __ldg(&g_D2[__byte_perm(wa, wb, 0x4436) & 0xFFFF]);
        uint4 h1 = __ldg(&g_H2[__byte_perm(wa, 0,  0x4412)]);
        uint4 h2 = __ldg(&g_H2[__byte_perm(wa, 0,  0x4423)]);

        unsigned a3x = __shfl_up_sync(FULL, a3.x, 1);
        unsigned a3y = __shfl_up_sync(FULL, a3.y, 1);
        unsigned h2z = __shfl_up_sync(FULL, h2.z, 1);
        unsigned h2w = __shfl_up_sync(FULL, h2.w, 1);
        if (lane == 0) {
            uint4 a1 = __ldg(&g_D2[__byte_perm(wa, wb, 0x4414) & 0xFFFF]);
            uint4 h0 = __ldg(&g_H2[__byte_perm(wa, 0,  0x4401)]);
            a3x = a1.x; a3y = a1.y;
            h2z = h0.z; h2w = h0.w;
        }

        acc_fwd(accP[0], v1.x, v1.y);
        acc_fwd(accP[1], v2.x, v2.y);
        acc_fwd(accP[0], m1.x, m1.y);
        acc_fwd(accP[1], m2.x, m2.y);
        acc_dl (accP[1], a2.x, a2.y);
        acc_dl (accP[0], a3x,  a3y);
        acc_fwd(accP[0], h1.x, h1.y);
        acc_rev(accP[1], h1.z, h1.w);
        acc_fwd(accP[1], h2.x, h2.y);
        acc_rev(accP[0], h2z,  h2w);

        size_t r0 = (size_t)(2 * (y0 + TH - 1)) * (2 * W0);
        float4 o0 = make_float4(accP[0][0], accP[0][1], accP[1][0], accP[1][1]);
        float4 o1 = make_float4(accP[0][2], accP[0][3], accP[1][2], accP[1][3]);
        *reinterpret_cast<float4*>(outp + r0)          = o0;
        *reinterpret_cast<float4*>(outp + r0 + 2 * W0) = o1;
    }
#undef LOADROW
}

extern "C" void kernel_launch(void* const* d_in, const int* in_sizes, int n_in,
                              void* d_out, int out_size)
{
    const int*    img = (const int*)d_in[0];
    const float4* hw  = (const float4*)d_in[1];
    const float4* dw  = (const float4*)d_in[2];
    const float4* vw  = (const float4*)d_in[3];
    float*        out = (float*)d_out;

    prep_kernel<<<256, 256>>>(hw, dw, vw);

    dim3 block(128, 1, 1);
    dim3 grid((W0 / 2) / 128, H0 / TH, BATCH);
    hdvlut_kernel<<<grid, block>>>(img, out);
}

// round 5
// speedup vs baseline: 1.6219x; 1.6219x over previous
#include <cuda_runtime.h>
#include <cuda_fp16.h>

#define W0 512
#define H0 512
#define BATCH 32
#define TH 8    // pixel rows per thread (two flat 4-row stages)

// Fused pair tables: entry e = p*256+q holds 8 halves:
//   [0..3] = 0.5 * T[p*256+q]  ("self")
//   [4..7] = 0.5 * T[q*256+p]  ("other")
__device__ uint4 g_H2[65536];
__device__ uint4 g_V2[65536];
__device__ uint4 g_D2[65536];

static __device__ __forceinline__ unsigned pack_h2(float a, float b) {
    __half2 h = __floats2half2_rn(a, b);
    return *reinterpret_cast<unsigned*>(&h);
}

__global__ void prep_kernel(const float4* __restrict__ hw,
                            const float4* __restrict__ dw,
                            const float4* __restrict__ vw)
{
    int e = blockIdx.x * blockDim.x + threadIdx.x;   // p*256 + q
    int p = e >> 8, q = e & 255;
    int et = (q << 8) | p;
    {
        float4 s = hw[e], o = hw[et];
        uint4 u;
        u.x = pack_h2(0.5f * s.x, 0.5f * s.y);
        u.y = pack_h2(0.5f * s.z, 0.5f * s.w);
        u.z = pack_h2(0.5f * o.x, 0.5f * o.y);
        u.w = pack_h2(0.5f * o.z, 0.5f * o.w);
        g_H2[e] = u;
    }
    {
        float4 s = vw[e], o = vw[et];
        uint4 u;
        u.x = pack_h2(0.5f * s.x, 0.5f * s.y);
        u.y = pack_h2(0.5f * s.z, 0.5f * s.w);
        u.z = pack_h2(0.5f * o.x, 0.5f * o.y);
        u.w = pack_h2(0.5f * o.z, 0.5f * o.w);
        g_V2[e] = u;
    }
    {
        float4 s = dw[e], o = dw[et];
        uint4 u;
        u.x = pack_h2(0.5f * s.x, 0.5f * s.y);
        u.y = pack_h2(0.5f * s.z, 0.5f * s.w);
        u.z = pack_h2(0.5f * o.x, 0.5f * o.y);
        u.w = pack_h2(0.5f * o.z, 0.5f * o.w);
        g_D2[e] = u;
    }
}

// ---- accumulation helpers (x,y are packed half2 pairs = 4 weights w=0..3) ----
static __device__ __forceinline__ void acc_fwd(float* a, unsigned x, unsigned y) {
    float2 p = __half22float2(*reinterpret_cast<__half2*>(&x));
    float2 q = __half22float2(*reinterpret_cast<__half2*>(&y));
    a[0] += p.x; a[1] += p.y; a[2] += q.x; a[3] += q.y;
}
static __device__ __forceinline__ void acc_rev(float* a, unsigned x, unsigned y) {
    float2 p = __half22float2(*reinterpret_cast<__half2*>(&x));
    float2 q = __half22float2(*reinterpret_cast<__half2*>(&y));
    a[3] += p.x; a[2] += p.y; a[1] += q.x; a[0] += q.y;
}
static __device__ __forceinline__ void acc_dl(float* a, unsigned x, unsigned y) {
    float2 p = __half22float2(*reinterpret_cast<__half2*>(&x));
    float2 q = __half22float2(*reinterpret_cast<__half2*>(&y));
    a[1] += p.x; a[3] += p.y; a[0] += q.x; a[2] += q.y;
}
static __device__ __forceinline__ void acc_ur(float* a, unsigned x, unsigned y) {
    float2 p = __half22float2(*reinterpret_cast<__half2*>(&x));
    float2 q = __half22float2(*reinterpret_cast<__half2*>(&y));
    a[2] += p.x; a[0] += p.y; a[3] += q.x; a[1] += q.y;
}

// Site-row gather block: pair rows (wa, wb). Declares v1,v2,m1,m2,a2,a3 (uint4)
// and shfl'd m2z,m2w (Dm other, c=0) and a3x,a3y (Da self, c=0), with lane-0
// fixups from its own left-boundary gathers.
#define SITE_LOAD(P, wa, wb)                                                   \
    uint4 P##v1 = __ldg(&g_V2[__byte_perm(wa, wb, 0x4415) & 0xFFFF]);          \
    uint4 P##v2 = __ldg(&g_V2[__byte_perm(wa, wb, 0x4426) & 0xFFFF]);          \
    uint4 P##m1 = __ldg(&g_D2[__byte_perm(wa, wb, 0x4416) & 0xFFFF]);          \
    uint4 P##m2 = __ldg(&g_D2[__byte_perm(wa, wb, 0x4427) & 0xFFFF]);          \
    uint4 P##a2 = __ldg(&g_D2[__byte_perm(wa, wb, 0x4425) & 0xFFFF]);          \
    uint4 P##a3 = __ldg(&g_D2[__byte_perm(wa, wb, 0x4436) & 0xFFFF]);          \
    unsigned P##m2z = __shfl_up_sync(0xFFFFFFFFu, P##m2.z, 1);                 \
    unsigned P##m2w = __shfl_up_sync(0xFFFFFFFFu, P##m2.w, 1);                 \
    unsigned P##a3x = __shfl_up_sync(0xFFFFFFFFu, P##a3.x, 1);                 \
    unsigned P##a3y = __shfl_up_sync(0xFFFFFFFFu, P##a3.y, 1);                 \
    if (lane == 0) {                                                           \
        uint4 _m0 = __ldg(&g_D2[__byte_perm(wa, wb, 0x4405) & 0xFFFF]);        \
        uint4 _a1 = __ldg(&g_D2[__byte_perm(wa, wb, 0x4414) & 0xFFFF]);        \
        P##m2z = _m0.z; P##m2w = _m0.w; P##a3x = _a1.x; P##a3y = _a1.y;        \
    }

// self contributions -> pixel row ABOVE the site row (rp = float[2][4])
#define SITE_SELF(P, rp)                                                       \
    acc_fwd(rp[0], P##v1.x, P##v1.y); acc_fwd(rp[1], P##v2.x, P##v2.y);        \
    acc_fwd(rp[0], P##m1.x, P##m1.y); acc_fwd(rp[1], P##m2.x, P##m2.y);        \
    acc_dl (rp[1], P##a2.x, P##a2.y); acc_dl (rp[0], P##a3x,  P##a3y);

// other contributions -> pixel row BELOW the site row
#define SITE_OTHER(P, rn)                                                      \
    acc_rev(rn[0], P##v1.z, P##v1.w); acc_rev(rn[1], P##v2.z, P##v2.w);        \
    acc_rev(rn[1], P##m1.z, P##m1.w); acc_rev(rn[0], P##m2z,  P##m2w);         \
    acc_ur (rn[0], P##a2.z, P##a2.w); acc_ur (rn[1], P##a3.z, P##a3.w);

// H sites for one pixel row (img word wa), accumulate into rp
#define H_ROW(rp, wa)                                                          \
    { uint4 _h1 = __ldg(&g_H2[__byte_perm(wa, 0, 0x4412)]);                    \
      uint4 _h2 = __ldg(&g_H2[__byte_perm(wa, 0, 0x4423)]);                    \
      unsigned _h2z = __shfl_up_sync(0xFFFFFFFFu, _h2.z, 1);                   \
      unsigned _h2w = __shfl_up_sync(0xFFFFFFFFu, _h2.w, 1);                   \
      if (lane == 0) {                                                         \
          uint4 _h0 = __ldg(&g_H2[__byte_perm(wa, 0, 0x4401)]);                \
          _h2z = _h0.z; _h2w = _h0.w;                                          \
      }                                                                        \
      acc_fwd(rp[0], _h1.x, _h1.y); acc_rev(rp[1], _h1.z, _h1.w);              \
      acc_fwd(rp[1], _h2.x, _h2.y); acc_rev(rp[0], _h2z,  _h2w); }

// store one finished pixel row (local row r in [0, TH))
#define STORE_ROW(rp, r)                                                       \
    { size_t _o = (size_t)(2 * (y0 + (r))) * (2 * W0);                         \
      *reinterpret_cast<float4*>(outp + _o) =                                  \
          make_float4(rp[0][0], rp[0][1], rp[1][0], rp[1][1]);                 \
      *reinterpret_cast<float4*>(outp + _o + 2 * W0) =                         \
          make_float4(rp[0][2], rp[0][3], rp[1][2], rp[1][3]); }

__global__ __launch_bounds__(128) void hdvlut_kernel(
    const int* __restrict__ img,
    float* __restrict__ out)
{
    int lane = threadIdx.x & 31;
    int x0 = (blockIdx.x * blockDim.x + threadIdx.x) * 2;
    int y0 = blockIdx.y * TH;
    int b  = blockIdx.z;

    const int* im = img + (size_t)b * (H0 * W0);
    int xs0 = max(x0 - 1, 0);
    int xs3 = min(x0 + 2, W0 - 1);

#define LOADROW(yy, dst) do {                                            \
        int _y = min(max((yy), 0), H0 - 1);                              \
        const int* _rp = im + _y * W0;                                   \
        unsigned _a0 = (unsigned)__ldg(_rp + xs0);                       \
        unsigned _a1 = (unsigned)__ldg(_rp + x0);                        \
        unsigned _a2 = (unsigned)__ldg(_rp + x0 + 1);                    \
        unsigned _a3 = (unsigned)__ldg(_rp + xs3);                       \
        dst = _a0 | (_a1 << 8) | (_a2 << 16) | (_a3 << 24);              \
    } while (0)

    float* outp = out + (size_t)b * (2 * H0) * (2 * W0) + 2 * x0;

    // ================= stage 1: pixel rows 0..3 =================
    unsigned w0, w1, w2, w3, w4, w5;
    LOADROW(y0 - 1, w0);
    LOADROW(y0,     w1);
    LOADROW(y0 + 1, w2);
    LOADROW(y0 + 2, w3);
    LOADROW(y0 + 3, w4);
    LOADROW(y0 + 4, w5);

    float A0[2][4] = {}, A1[2][4] = {}, A2[2][4] = {}, A3[2][4] = {};

    { SITE_LOAD(s0, w0, w1); SITE_OTHER(s0, A0); }                 // site 0
    { SITE_LOAD(s1, w1, w2); SITE_SELF(s1, A0); SITE_OTHER(s1, A1); }
    H_ROW(A0, w1);
    { SITE_LOAD(s2, w2, w3); SITE_SELF(s2, A1); SITE_OTHER(s2, A2); }
    H_ROW(A1, w2);
    { SITE_LOAD(s3, w3, w4); SITE_SELF(s3, A2); SITE_OTHER(s3, A3); }
    H_ROW(A2, w3);

    // boundary site 4: self -> A3 now, carry others for stage 2
    unsigned cv1z, cv1w, cv2z, cv2w, cm1z, cm1w, cm2z, cm2w, ca2z, ca2w, ca3z, ca3w;
    {
        SITE_LOAD(s4, w4, w5);
        SITE_SELF(s4, A3);
        cv1z = s4v1.z; cv1w = s4v1.w; cv2z = s4v2.z; cv2w = s4v2.w;
        cm1z = s4m1.z; cm1w = s4m1.w; cm2z = s4m2z;  cm2w = s4m2w;
        ca2z = s4a2.z; ca2w = s4a2.w; ca3z = s4a3.z; ca3w = s4a3.w;
    }
    H_ROW(A3, w4);

    STORE_ROW(A0, 0); STORE_ROW(A1, 1); STORE_ROW(A2, 2); STORE_ROW(A3, 3);

    // ================= stage 2: pixel rows 4..7 =================
    unsigned w6, w7, w8, w9;
    LOADROW(y0 + 5, w6);
    LOADROW(y0 + 6, w7);
    LOADROW(y0 + 7, w8);
    LOADROW(y0 + 8, w9);

    float B0[2][4] = {}, B1[2][4] = {}, B2[2][4] = {}, B3[2][4] = {};

    // carried others from site 4 -> pixel row 4
    acc_rev(B0[0], cv1z, cv1w); acc_rev(B0[1], cv2z, cv2w);
    acc_rev(B0[1], cm1z, cm1w); acc_rev(B0[0], cm2z, cm2w);
    acc_ur (B0[0], ca2z, ca2w); acc_ur (B0[1], ca3z, ca3w);

    { SITE_LOAD(s5, w5, w6); SITE_SELF(s5, B0); SITE_OTHER(s5, B1); }
    H_ROW(B0, w5);
    { SITE_LOAD(s6, w6, w7); SITE_SELF(s6, B1); SITE_OTHER(s6, B2); }
    H_ROW(B1, w6);
    { SITE_LOAD(s7, w7, w8); SITE_SELF(s7, B2); SITE_OTHER(s7, B3); }
    H_ROW(B2, w7);
    { SITE_LOAD(s8, w8, w9); SITE_SELF(s8, B3); }                  // site 8: self only
    H_ROW(B3, w8);

    STORE_ROW(B0, 4); STORE_ROW(B1, 5); STORE_ROW(B2, 6); STORE_ROW(B3, 7);

#undef LOADROW
}

extern "C" void kernel_launch(void* const* d_in, const int* in_sizes, int n_in,
                              void* d_out, int out_size)
{
    const int*    img = (const int*)d_in[0];
    const float4* hw  = (const float4*)d_in[1];
    const float4* dw  = (const float4*)d_in[2];
    const float4* vw  = (const float4*)d_in[3];
    float*        out = (float*)d_out;

    prep_kernel<<<256, 256>>>(hw, dw, vw);

    dim3 block(128, 1, 1);
    dim3 grid((W0 / 2) / 128, H0 / TH, BATCH);
    hdvlut_kernel<<<grid, block>>>(img, out);
}